// round 8
// baseline (speedup 1.0000x reference)
#include <cuda_runtime.h>
#include <cuda_bf16.h>
#include <cstdint>

// Problem constants
#define B_   64
#define L_   4096
#define KD_  128
#define H_   4
#define OUT_ 256

#define CHUNKS 16                // L-chunks per batch (pass 1)
#define WARPS  4                 // warps per block in pass 1 (128 threads)
#define ROWS_PER_WARP (L_ / CHUNKS / WARPS)   // 64 rows = two 32-bit bitmaps
#define NBLK1 (B_ * CHUNKS)      // 1024

typedef unsigned long long u64;

// Deterministic scratch (no device allocation allowed)
__device__ float g_pacc[NBLK1][KD_ * H_];   // 1024 x 512 f32 = 2 MB
__device__ float g_pZ[NBLK1][H_];
__device__ float g_pooled[B_][KD_ * H_];    // normalized pooled vectors

__device__ __forceinline__ float warp_sum32(float v) {
#pragma unroll
    for (int off = 16; off >= 1; off >>= 1)
        v += __shfl_xor_sync(0xffffffffu, v, off);
    return v;
}

// Packed f32x2 helpers (sm_103a: FFMA2 reachable only via PTX f32x2 ops)
#define PACK2(d, lo, hi)  asm("mov.b64 %0, {%1, %2};" : "=l"(d) : "f"(lo), "f"(hi))
#define UNPACK2(lo, hi, s) asm("mov.b64 {%0, %1}, %2;" : "=f"(lo), "=f"(hi) : "l"(s))
#define MUL2(d, a, b)     asm("mul.rn.f32x2 %0, %1, %2;" : "=l"(d) : "l"(a), "l"(b))
#define FMA2(d, a, b, c)  asm("fma.rn.f32x2 %0, %1, %2, %3;" : "=l"(d) : "l"(a), "l"(b), "l"(c))

// Fresh global load (volatile asm defeats CSE with the earlier load of the
// same address, so xv[] need not stay live across the butterfly -> fewer regs;
// the data is L1-hot).
__device__ __forceinline__ float4 ldg_v4_fresh(const void* p) {
    float4 r;
    asm volatile("ld.global.v4.f32 {%0,%1,%2,%3}, [%4];"
                 : "=f"(r.x), "=f"(r.y), "=f"(r.z), "=f"(r.w) : "l"(p));
    return r;
}

// ---------------------------------------------------------------------------
// Pass 1. Warp owns 64 rows as two 32-bit mask bitmaps. Live rows processed
// 8 per iteration: per-lane dot partials for 8 rows x 4 heads = 32 values,
// reduced by ONE 5-level butterfly transpose-reduce (31 SHFL); lane l ends
// holding the full score of (row l>>2, head l&3) -> one __expf per lane per
// 8 rows. Dot and accumulate use packed f32x2 FMA (FFMA2). x rows are
// re-loaded from L1 for the accumulate instead of staying in registers.
// exp(-1e9)==0 in fp32 => skipping masked rows is exact; |score|<~4 => no
// max subtraction needed.
// ---------------------------------------------------------------------------
__global__ void __launch_bounds__(128, 6)
pool_pass1(const float* __restrict__ x,
           const int* __restrict__ mask,   // bool coerced to int32 by harness
           const float* __restrict__ q)
{
    const int blk  = blockIdx.x;
    const int b    = blk / CHUNKS;
    const int c    = blk % CHUNKS;
    const int w    = threadIdx.x >> 5;
    const int lane = threadIdx.x & 31;

    __shared__ float sP[WARPS][32];         // softmax-weight broadcast
    __shared__ float sAcc[WARPS][KD_ * H_];
    __shared__ float sZ[WARPS][H_];

    // queries: lane owns floats [lane*4, lane*4+4) of each head's vector.
    // Pack per-component head-pairs for f32x2 dot:
    u64 qx01, qy01, qz01, qw01, qx23, qy23, qz23, qw23;
    {
        float4 q0 = *reinterpret_cast<const float4*>(q + 0 * KD_ + lane * 4);
        float4 q1 = *reinterpret_cast<const float4*>(q + 1 * KD_ + lane * 4);
        float4 q2 = *reinterpret_cast<const float4*>(q + 2 * KD_ + lane * 4);
        float4 q3 = *reinterpret_cast<const float4*>(q + 3 * KD_ + lane * 4);
        PACK2(qx01, q0.x, q1.x); PACK2(qy01, q0.y, q1.y);
        PACK2(qz01, q0.z, q1.z); PACK2(qw01, q0.w, q1.w);
        PACK2(qx23, q2.x, q3.x); PACK2(qy23, q2.y, q3.y);
        PACK2(qz23, q2.z, q3.z); PACK2(qw23, q2.w, q3.w);
    }

    // Accumulators: acc01[j] = (acc[j][h0], acc[j][h1]), acc23[j] = (h2,h3)
    u64 acc01[4], acc23[4];
    {
        const float z = 0.0f;
#pragma unroll
        for (int j = 0; j < 4; j++) { PACK2(acc01[j], z, z); PACK2(acc23[j], z, z); }
    }
    float zacc = 0.0f;

    const int l0 = c * (L_ / CHUNKS) + w * ROWS_PER_WARP;
    const float* xb = x + (size_t)b * L_ * KD_ + (size_t)l0 * KD_;
    const int* mb = mask + (size_t)b * L_ + l0;

#pragma unroll 1
    for (int half = 0; half < 2; half++) {
        unsigned m = __ballot_sync(0xffffffffu, mb[half * 32 + lane] != 0);
        const char* baseL = (const char*)(xb + (size_t)half * 32 * KD_) + lane * 16;

        while (m) {
            // ---- extract up to 8 live rows (32-bit bitmap: cheap ALU) ----
            int r[8];
            unsigned live = 0;
            r[0] = 0;
#pragma unroll
            for (int i = 0; i < 8; i++) {
                if (m) {
                    r[i] = __ffs(m) - 1;
                    m &= m - 1;
                    live |= 1u << i;
                } else {
                    r[i] = r[0];         // padded duplicate, zero-weighted
                }
            }

            // ---- load 8 rows, f32x2 dot partials -> v[32] ----
            float v[32];
#pragma unroll
            for (int i = 0; i < 8; i++) {
                const float4 xv = *reinterpret_cast<const float4*>(baseL + ((unsigned)r[i] << 9));
                u64 xx2, xy2, xz2, xw2, t01, t23;
                PACK2(xx2, xv.x, xv.x); PACK2(xy2, xv.y, xv.y);
                PACK2(xz2, xv.z, xv.z); PACK2(xw2, xv.w, xv.w);
                MUL2(t01, xx2, qx01);
                FMA2(t01, xy2, qy01, t01);
                FMA2(t01, xz2, qz01, t01);
                FMA2(t01, xw2, qw01, t01);
                MUL2(t23, xx2, qx23);
                FMA2(t23, xy2, qy23, t23);
                FMA2(t23, xz2, qz23, t23);
                FMA2(t23, xw2, qw23, t23);
                UNPACK2(v[i * 4 + 0], v[i * 4 + 1], t01);
                UNPACK2(v[i * 4 + 2], v[i * 4 + 3], t23);
            }

            // ---- 32-value butterfly transpose-reduce (31 SHFL, 5 levels) ----
            // End: v[0] on lane l == full 32-lane sum of value l.
#pragma unroll
            for (int step = 0; step < 5; step++) {
                const int off    = 16 >> step;
                const int half_n = 16 >> step;
                const bool up = (lane & off) != 0;
#pragma unroll
                for (int i = 0; i < 16; i++) {
                    if (i < half_n) {
                        const float send = up ? v[i] : v[i + half_n];
                        const float recv = __shfl_xor_sync(0xffffffffu, send, off);
                        v[i] = (up ? v[i + half_n] : v[i]) + recv;
                    }
                }
            }

            // ---- softmax weight: lane l = (row l>>2, head l&3) ----
            float e = __expf(v[0]);
            e = ((live >> (lane >> 2)) & 1u) ? e : 0.0f;
            __syncwarp();
            sP[w][lane] = e;
            __syncwarp();
            zacc += e;                     // Z[lane&3] partial

            // ---- accumulate 8 rows (x re-loaded from L1, f32x2 FMA) ----
#pragma unroll
            for (int i = 0; i < 8; i++) {
                const float4 xr = ldg_v4_fresh(baseL + ((unsigned)r[i] << 9));
                const float4 pv = *reinterpret_cast<const float4*>(&sP[w][i * 4]);
                u64 p01, p23, xj2;
                PACK2(p01, pv.x, pv.y);
                PACK2(p23, pv.z, pv.w);
                PACK2(xj2, xr.x, xr.x);
                FMA2(acc01[0], xj2, p01, acc01[0]);
                FMA2(acc23[0], xj2, p23, acc23[0]);
                PACK2(xj2, xr.y, xr.y);
                FMA2(acc01[1], xj2, p01, acc01[1]);
                FMA2(acc23[1], xj2, p23, acc23[1]);
                PACK2(xj2, xr.z, xr.z);
                FMA2(acc01[2], xj2, p01, acc01[2]);
                FMA2(acc23[2], xj2, p23, acc23[2]);
                PACK2(xj2, xr.w, xr.w);
                FMA2(acc01[3], xj2, p01, acc01[3]);
                FMA2(acc23[3], xj2, p23, acc23[3]);
            }
            __syncwarp();                  // protect sP before next overwrite
        }
    }

    // Z[h] = sum over lanes with (lane&3)==h -> lanes 0..3
    float zz = zacc;
#pragma unroll
    for (int off = 16; off >= 4; off >>= 1)
        zz += __shfl_xor_sync(0xffffffffu, zz, off);

    // ---- block-level deterministic reduce ----
#pragma unroll
    for (int j = 0; j < 4; j++) {
        float h0, h1, h2, h3;
        UNPACK2(h0, h1, acc01[j]);
        UNPACK2(h2, h3, acc23[j]);
        const int k = lane * 4 + j;        // k index in [0,128)
        sAcc[w][k * H_ + 0] = h0;
        sAcc[w][k * H_ + 1] = h1;
        sAcc[w][k * H_ + 2] = h2;
        sAcc[w][k * H_ + 3] = h3;
    }
    if (lane < H_) sZ[w][lane] = zz;
    __syncthreads();

    for (int idx = threadIdx.x; idx < KD_ * H_; idx += 128) {
        float vv = 0.f;
#pragma unroll
        for (int ww = 0; ww < WARPS; ww++) vv += sAcc[ww][idx];
        g_pacc[blk][idx] = vv;
    }
    if (threadIdx.x < H_) {
        float vv = 0.f;
#pragma unroll
        for (int ww = 0; ww < WARPS; ww++) vv += sZ[ww][threadIdx.x];
        g_pZ[blk][threadIdx.x] = vv;
    }
}

// ---------------------------------------------------------------------------
// Pass 2a: combine chunk partials + normalize -> g_pooled[b][*].
// 64 blocks x 512 threads: one thread per pooled element, 16 independent loads.
// ---------------------------------------------------------------------------
__global__ void __launch_bounds__(512, 2)
pool_combine()
{
    const int b   = blockIdx.x;
    const int tid = threadIdx.x;
    __shared__ float Zs[H_];

    if (tid < H_) {
        float vv = 0.f;
#pragma unroll
        for (int c = 0; c < CHUNKS; c++) vv += g_pZ[b * CHUNKS + c][tid];
        Zs[tid] = vv;
    }
    float vv = 0.f;
#pragma unroll
    for (int c = 0; c < CHUNKS; c++) vv += g_pacc[b * CHUNKS + c][tid];
    __syncthreads();
    g_pooled[b][tid] = vv / Zs[tid & (H_ - 1)];
}

// ---------------------------------------------------------------------------
// Pass 2b: out = relu(pooled @ W^T + b + relu(emb[num])).
// Grid = B * 8 blocks (batch x 32-output group); warp computes 4 outputs
// from 16 independent W float4 loads against smem-cached pooled.
// ---------------------------------------------------------------------------
__global__ void __launch_bounds__(256, 4)
pool_gemv(const float* __restrict__ W,
          const float* __restrict__ bias,
          const float* __restrict__ emb,
          const int* __restrict__ num,
          float* __restrict__ out)
{
    const int b    = blockIdx.x >> 3;
    const int og   = blockIdx.x & 7;
    const int tid  = threadIdx.x;
    const int wrp  = tid >> 5;
    const int lane = tid & 31;
    const int o0   = og * 32 + wrp * 4;

    __shared__ float pooled[KD_ * H_];
    for (int idx = tid; idx < (KD_ * H_) / 4; idx += 256)
        reinterpret_cast<float4*>(pooled)[idx] =
            reinterpret_cast<const float4*>(g_pooled[b])[idx];
    __syncthreads();

    float4 pv[4];
#pragma unroll
    for (int qi = 0; qi < 4; qi++)
        pv[qi] = *reinterpret_cast<const float4*>(&pooled[qi * 128 + lane * 4]);

    float a[4];
#pragma unroll
    for (int j = 0; j < 4; j++) {
        const float* Wr = W + (size_t)(o0 + j) * (KD_ * H_);
        float ssum = 0.f;
#pragma unroll
        for (int qi = 0; qi < 4; qi++) {
            const float4 wv = *reinterpret_cast<const float4*>(Wr + qi * 128 + lane * 4);
            ssum = fmaf(wv.x, pv[qi].x, fmaf(wv.y, pv[qi].y,
                   fmaf(wv.z, pv[qi].z, fmaf(wv.w, pv[qi].w, ssum))));
        }
        a[j] = warp_sum32(ssum);
    }

    if (lane == 0) {
        const int nb = num[b];
#pragma unroll
        for (int j = 0; j < 4; j++) {
            const int o = o0 + j;
            float vv = a[j] + bias[o] + fmaxf(emb[(size_t)nb * OUT_ + o], 0.f);
            out[(size_t)b * OUT_ + o] = fmaxf(vv, 0.f);
        }
    }
}

// ---------------------------------------------------------------------------
// Launch.  Inputs (metadata order): x, mask, num, queries, W, b, emb
// ---------------------------------------------------------------------------
extern "C" void kernel_launch(void* const* d_in, const int* in_sizes, int n_in,
                              void* d_out, int out_size)
{
    const float* x    = (const float*)d_in[0];
    const int*   mask = (const int*)d_in[1];     // bool -> int32 on upload
    const int*   num  = (const int*)d_in[2];
    const float* q    = (const float*)d_in[3];
    const float* W    = (const float*)d_in[4];
    const float* bias = (const float*)d_in[5];
    const float* emb  = (const float*)d_in[6];
    float*       out  = (float*)d_out;

    pool_pass1<<<NBLK1, 128>>>(x, mask, q);
    pool_combine<<<B_, 512>>>();
    pool_gemv<<<B_ * 8, 256>>>(W, bias, emb, num, out);
}

// round 9
// speedup vs baseline: 1.0849x; 1.0849x over previous
#include <cuda_runtime.h>
#include <cuda_bf16.h>
#include <cstdint>

// Problem constants
#define B_   64
#define L_   4096
#define KD_  128
#define H_   4
#define OUT_ 256

#define CHUNKS 16                // L-chunks per batch (pass 1)
#define WARPS  4                 // warps per block in pass 1 (128 threads)
#define ROWS_PER_WARP (L_ / CHUNKS / WARPS)   // 64 rows = two 32-row halves
#define NBLK1 (B_ * CHUNKS)      // 1024

// Deterministic scratch (no device allocation allowed)
__device__ float g_pacc[NBLK1][KD_ * H_];   // 1024 x 512 f32 = 2 MB
__device__ float g_pZ[NBLK1][H_];
__device__ float g_pooled[B_][KD_ * H_];    // normalized pooled vectors

__device__ __forceinline__ float warp_sum32(float v) {
#pragma unroll
    for (int off = 16; off >= 1; off >>= 1)
        v += __shfl_xor_sync(0xffffffffu, v, off);
    return v;
}

// Pop up to 4 set bits from a 32-bit mask; returns slot-liveness mask.
__device__ __forceinline__ unsigned extract4(unsigned& m, int r[4]) {
    unsigned live = 0;
    r[0] = 0;
#pragma unroll
    for (int i = 0; i < 4; i++) {
        if (m) {
            r[i] = __ffs(m) - 1;
            m &= m - 1;
            live |= 1u << i;
        } else {
            r[i] = r[0];               // padded duplicate, zero-weighted
        }
    }
    return live;
}

// ---------------------------------------------------------------------------
// Pass 1. Warp owns 64 rows as two 32-bit mask bitmaps; live rows processed
// 4 per iteration (no prefetch — occupancy is the latency hider).
// Scores: 4 rows x 4 heads = 16 values; 4-level butterfly (offsets 8,4,2,1)
// transpose-reduces within each 16-lane half, then one offset-16 exchange
// adds the two half-sums -> every lane l holds the full score of value
// (l & 15) = (row (l&15)>>2, head l&3). One __expf per lane per 4 rows.
// Weights broadcast via double-buffered smem (one __syncwarp per iter).
// exp(-1e9)==0 in fp32 => skipping masked rows is exact; |score|<~4 => no
// max subtraction needed.
// ---------------------------------------------------------------------------
__global__ void __launch_bounds__(128, 6)
pool_pass1(const float* __restrict__ x,
           const int* __restrict__ mask,   // bool coerced to int32 by harness
           const float* __restrict__ q)
{
    const int blk  = blockIdx.x;
    const int b    = blk / CHUNKS;
    const int c    = blk % CHUNKS;
    const int w    = threadIdx.x >> 5;
    const int lane = threadIdx.x & 31;

    __shared__ float sP[WARPS][2][16];      // double-buffered weight broadcast
    __shared__ float sAcc[WARPS][KD_ * H_];
    __shared__ float sZ[WARPS][H_];

    float4 q4[H_];
#pragma unroll
    for (int h = 0; h < H_; h++)
        q4[h] = *reinterpret_cast<const float4*>(q + h * KD_ + lane * 4);

    float acc[4][H_];
#pragma unroll
    for (int j = 0; j < 4; j++)
#pragma unroll
        for (int h = 0; h < H_; h++) acc[j][h] = 0.0f;
    float zacc = 0.0f;

    const int l0 = c * (L_ / CHUNKS) + w * ROWS_PER_WARP;
    const float* xb = x + (size_t)b * L_ * KD_ + (size_t)l0 * KD_;
    const int* mb = mask + (size_t)b * L_ + l0;

    int pb = 0;
#pragma unroll 1
    for (int half = 0; half < 2; half++) {
        unsigned m = __ballot_sync(0xffffffffu, mb[half * 32 + lane] != 0);
        const char* baseL = (const char*)(xb + (size_t)half * 32 * KD_) + lane * 16;

        while (m) {
            int r[4];
            const unsigned live = extract4(m, r);

            float4 xv[4];
#pragma unroll
            for (int i = 0; i < 4; i++)
                xv[i] = *reinterpret_cast<const float4*>(baseL + ((unsigned)r[i] << 9));

            // ---- per-lane dot partials: v[slot*4+h] ----
            float v[16];
#pragma unroll
            for (int i = 0; i < 4; i++)
#pragma unroll
                for (int h = 0; h < H_; h++)
                    v[i * 4 + h] = xv[i].x * q4[h].x + xv[i].y * q4[h].y
                                 + xv[i].z * q4[h].z + xv[i].w * q4[h].w;

            // ---- 4-level butterfly transpose-reduce within 16-lane halves ----
#pragma unroll
            for (int step = 0; step < 4; step++) {
                const int off = 8 >> step;
                const bool up = (lane & off) != 0;
#pragma unroll
                for (int i = 0; i < 8; i++) {
                    if (i < (8 >> step)) {
                        const float send = up ? v[i] : v[i + (8 >> step)];
                        const float recv = __shfl_xor_sync(0xffffffffu, send, off);
                        v[i] = (up ? v[i + (8 >> step)] : v[i]) + recv;
                    }
                }
            }
            // Combine the two half-sums -> full 32-lane dot product.
            v[0] += __shfl_xor_sync(0xffffffffu, v[0], 16);

            // ---- softmax weight: lane l holds value (l & 15) ----
            float e = __expf(v[0]);
            const unsigned s = (lane & 15) >> 2;
            e = ((live >> s) & 1u) ? e : 0.0f;
            if (lane < 16) sP[w][pb][lane] = e; else e = 0.0f;
            __syncwarp();
            zacc += e;                     // Z[lane&3] partial (lanes<16 only)

            // ---- accumulate 4 rows ----
#pragma unroll
            for (int i = 0; i < 4; i++) {
                const float4 pv = *reinterpret_cast<const float4*>(&sP[w][pb][i * 4]);
                acc[0][0] = fmaf(xv[i].x, pv.x, acc[0][0]);
                acc[0][1] = fmaf(xv[i].x, pv.y, acc[0][1]);
                acc[0][2] = fmaf(xv[i].x, pv.z, acc[0][2]);
                acc[0][3] = fmaf(xv[i].x, pv.w, acc[0][3]);
                acc[1][0] = fmaf(xv[i].y, pv.x, acc[1][0]);
                acc[1][1] = fmaf(xv[i].y, pv.y, acc[1][1]);
                acc[1][2] = fmaf(xv[i].y, pv.z, acc[1][2]);
                acc[1][3] = fmaf(xv[i].y, pv.w, acc[1][3]);
                acc[2][0] = fmaf(xv[i].z, pv.x, acc[2][0]);
                acc[2][1] = fmaf(xv[i].z, pv.y, acc[2][1]);
                acc[2][2] = fmaf(xv[i].z, pv.z, acc[2][2]);
                acc[2][3] = fmaf(xv[i].z, pv.w, acc[2][3]);
                acc[3][0] = fmaf(xv[i].w, pv.x, acc[3][0]);
                acc[3][1] = fmaf(xv[i].w, pv.y, acc[3][1]);
                acc[3][2] = fmaf(xv[i].w, pv.z, acc[3][2]);
                acc[3][3] = fmaf(xv[i].w, pv.w, acc[3][3]);
            }
            pb ^= 1;                       // safe: next write is other buffer;
                                           // reuse of this one is fenced by the
                                           // syncwarp of the following iter.
        }
    }

    // Z[h] = sum over lanes with (lane&3)==h -> lanes 0..3
    float zz = zacc;
#pragma unroll
    for (int off = 16; off >= 4; off >>= 1)
        zz += __shfl_xor_sync(0xffffffffu, zz, off);

    // ---- block-level deterministic reduce ----
#pragma unroll
    for (int j = 0; j < 4; j++)
#pragma unroll
        for (int h = 0; h < H_; h++)
            sAcc[w][(lane * 4 + j) * H_ + h] = acc[j][h];   // idx = k*H + h
    if (lane < H_) sZ[w][lane] = zz;
    __syncthreads();

    for (int idx = threadIdx.x; idx < KD_ * H_; idx += 128) {
        float vv = 0.f;
#pragma unroll
        for (int ww = 0; ww < WARPS; ww++) vv += sAcc[ww][idx];
        g_pacc[blk][idx] = vv;
    }
    if (threadIdx.x < H_) {
        float vv = 0.f;
#pragma unroll
        for (int ww = 0; ww < WARPS; ww++) vv += sZ[ww][threadIdx.x];
        g_pZ[blk][threadIdx.x] = vv;
    }
}

// ---------------------------------------------------------------------------
// Pass 2a: combine chunk partials + normalize -> g_pooled[b][*].
// 64 blocks x 512 threads: one thread per pooled element, 16 independent loads.
// ---------------------------------------------------------------------------
__global__ void __launch_bounds__(512, 2)
pool_combine()
{
    const int b   = blockIdx.x;
    const int tid = threadIdx.x;
    __shared__ float Zs[H_];

    if (tid < H_) {
        float vv = 0.f;
#pragma unroll
        for (int c = 0; c < CHUNKS; c++) vv += g_pZ[b * CHUNKS + c][tid];
        Zs[tid] = vv;
    }
    float vv = 0.f;
#pragma unroll
    for (int c = 0; c < CHUNKS; c++) vv += g_pacc[b * CHUNKS + c][tid];
    __syncthreads();
    g_pooled[b][tid] = vv / Zs[tid & (H_ - 1)];
}

// ---------------------------------------------------------------------------
// Pass 2b: out = relu(pooled @ W^T + b + relu(emb[num])).
// Grid = B * 8 blocks (batch x 32-output group); warp computes 4 outputs
// from 16 independent W float4 loads against smem-cached pooled.
// ---------------------------------------------------------------------------
__global__ void __launch_bounds__(256, 4)
pool_gemv(const float* __restrict__ W,
          const float* __restrict__ bias,
          const float* __restrict__ emb,
          const int* __restrict__ num,
          float* __restrict__ out)
{
    const int b    = blockIdx.x >> 3;
    const int og   = blockIdx.x & 7;
    const int tid  = threadIdx.x;
    const int wrp  = tid >> 5;
    const int lane = tid & 31;
    const int o0   = og * 32 + wrp * 4;

    __shared__ float pooled[KD_ * H_];
    for (int idx = tid; idx < (KD_ * H_) / 4; idx += 256)
        reinterpret_cast<float4*>(pooled)[idx] =
            reinterpret_cast<const float4*>(g_pooled[b])[idx];
    __syncthreads();

    float4 pv[4];
#pragma unroll
    for (int qi = 0; qi < 4; qi++)
        pv[qi] = *reinterpret_cast<const float4*>(&pooled[qi * 128 + lane * 4]);

    float a[4];
#pragma unroll
    for (int j = 0; j < 4; j++) {
        const float* Wr = W + (size_t)(o0 + j) * (KD_ * H_);
        float ssum = 0.f;
#pragma unroll
        for (int qi = 0; qi < 4; qi++) {
            const float4 wv = *reinterpret_cast<const float4*>(Wr + qi * 128 + lane * 4);
            ssum = fmaf(wv.x, pv[qi].x, fmaf(wv.y, pv[qi].y,
                   fmaf(wv.z, pv[qi].z, fmaf(wv.w, pv[qi].w, ssum))));
        }
        a[j] = warp_sum32(ssum);
    }

    if (lane == 0) {
        const int nb = num[b];
#pragma unroll
        for (int j = 0; j < 4; j++) {
            const int o = o0 + j;
            float vv = a[j] + bias[o] + fmaxf(emb[(size_t)nb * OUT_ + o], 0.f);
            out[(size_t)b * OUT_ + o] = fmaxf(vv, 0.f);
        }
    }
}

// ---------------------------------------------------------------------------
// Launch.  Inputs (metadata order): x, mask, num, queries, W, b, emb
// ---------------------------------------------------------------------------
extern "C" void kernel_launch(void* const* d_in, const int* in_sizes, int n_in,
                              void* d_out, int out_size)
{
    const float* x    = (const float*)d_in[0];
    const int*   mask = (const int*)d_in[1];     // bool -> int32 on upload
    const int*   num  = (const int*)d_in[2];
    const float* q    = (const float*)d_in[3];
    const float* W    = (const float*)d_in[4];
    const float* bias = (const float*)d_in[5];
    const float* emb  = (const float*)d_in[6];
    float*       out  = (float*)d_out;

    pool_pass1<<<NBLK1, 128>>>(x, mask, q);
    pool_combine<<<B_, 512>>>();
    pool_gemv<<<B_ * 8, 256>>>(W, bias, emb, num, out);
}